// round 16
// baseline (speedup 1.0000x reference)
#include <cuda_runtime.h>
#include <math.h>

#define T_  512
#define N_  256
#define H_  256
#define HR_ 64
#define V_  64

typedef unsigned long long U64;

__device__ __forceinline__ U64 pack_dup(float x){ U64 r; asm("mov.b64 %0, {%1, %1};" : "=l"(r) : "f"(x)); return r; }
__device__ __forceinline__ U64 fma2(U64 a, U64 b, U64 c){ U64 d; asm("fma.rn.f32x2 %0, %1, %2, %3;" : "=l"(d) : "l"(a), "l"(b), "l"(c)); return d; }
__device__ __forceinline__ U64 add2(U64 a, U64 b){ U64 d; asm("add.rn.f32x2 %0, %1, %2;" : "=l"(d) : "l"(a), "l"(b)); return d; }
__device__ __forceinline__ float2 u2f(U64 v){ float2 f; asm("mov.b64 {%0, %1}, %2;" : "=f"(f.x), "=f"(f.y) : "l"(v)); return f; }
__device__ __forceinline__ float sigm(float x){ return 1.f / (1.f + expf(-x)); }
// L2-coherent loads — REQUIRED for data produced by a concurrently-running kernel
__device__ __forceinline__ float ldcg(const float* p){
    float v; asm volatile("ld.global.cg.f32 %0, [%1];" : "=f"(v) : "l"(p)); return v;
}
__device__ __forceinline__ float4 ldcg4(const float* p){
    float4 v; asm volatile("ld.global.cg.v4.f32 {%0,%1,%2,%3}, [%4];"
        : "=f"(v.x), "=f"(v.y), "=f"(v.z), "=f"(v.w) : "l"(p)); return v;
}

__device__ float d_M  [N_*HR_*H_];
__device__ float d_GIf[N_*HR_*3*H_];
__device__ float d_GIb[N_*HR_*3*H_];
__device__ float d_K  [N_*HR_*2*H_];
__device__ float d_Xin[T_*N_*(V_+H_)];
__device__ float d_X0 [T_*N_*H_];
__device__ float d_X1 [T_*N_*H_];
__device__ float d_GIc[T_*N_*3*H_];
__device__ float d_H  [T_*N_*H_];
__device__ float d_Ht [T_*N_*H_];          // [t][col][n]
__device__ float d_Kt [2*HR_*N_*H_];       // [dir][s][col][n]
__device__ float d_G  [N_*HR_*H_];         // [n][s][j]  = K[n,s,:]@qg_W^T
__device__ float d_Wt [2*H_*H_];           // qg_W^T (512,256)
__device__ float d_cv [N_*HR_];            // c[n,s] = qg_b . K[n,s,:]
__device__ float d_Lg [T_*N_*HR_];
__device__ float d_Z  [H_];                // zeros (never written)
__device__ unsigned d_barE[8*32], d_barC[8*32];
__device__ unsigned d_prog;                // GIc chunks completed (0..8)
__device__ unsigned d_progH;               // H 128-step blocks: 128 arrivals each

__global__ void zero_bars(){
    if (threadIdx.x < 256) d_barE[threadIdx.x] = 0u;
    if (threadIdx.x < 256) d_barC[threadIdx.x] = 0u;
    if (threadIdx.x == 0){ d_prog = 0u; d_progH = 0u; }
}

__global__ void set_prog(unsigned v){ d_prog = v; }

// ---------------- fp32 GEMM (FFMA2), tile 128x64  (proven — DO NOT TOUCH) -------
template<bool RELU>
__global__ void __launch_bounds__(256) gemm_nn(
    const float* __restrict__ A, int lda, const float* __restrict__ B, int ldb,
    const float* __restrict__ bias, float* __restrict__ C, int ldc, int Kd)
{
    __shared__ __align__(16) float As[16][128];
    __shared__ __align__(16) float Bs[16][64];
    const int m0 = blockIdx.y * 128, n0 = blockIdx.x * 64;
    const int tid = threadIdx.x, tx = tid & 15, ty = tid >> 4;
    U64 acc[4][4] = {};
    for (int k0 = 0; k0 < Kd; k0 += 16){
        #pragma unroll
        for (int l = 0; l < 2; l++){
            int q = tid + l*256, row = q >> 2, c4 = q & 3;
            float4 f = *(const float4*)&A[(size_t)(m0+row)*lda + k0 + c4*4];
            As[c4*4+0][row] = f.x; As[c4*4+1][row] = f.y;
            As[c4*4+2][row] = f.z; As[c4*4+3][row] = f.w;
        }
        {
            int kr = tid >> 4, c4 = tid & 15;
            *(float4*)&Bs[kr][c4*4] = *(const float4*)&B[(size_t)(k0+kr)*ldb + n0 + c4*4];
        }
        __syncthreads();
        #pragma unroll
        for (int k = 0; k < 16; k++){
            const U64* ap = (const U64*)&As[k][ty*8];
            U64 a0 = ap[0], a1 = ap[1], a2 = ap[2], a3 = ap[3];
            float4 bv = *(const float4*)&Bs[k][tx*4];
            U64 b0 = pack_dup(bv.x), b1 = pack_dup(bv.y);
            U64 b2 = pack_dup(bv.z), b3 = pack_dup(bv.w);
            acc[0][0]=fma2(a0,b0,acc[0][0]); acc[0][1]=fma2(a0,b1,acc[0][1]);
            acc[0][2]=fma2(a0,b2,acc[0][2]); acc[0][3]=fma2(a0,b3,acc[0][3]);
            acc[1][0]=fma2(a1,b0,acc[1][0]); acc[1][1]=fma2(a1,b1,acc[1][1]);
            acc[1][2]=fma2(a1,b2,acc[1][2]); acc[1][3]=fma2(a1,b3,acc[1][3]);
            acc[2][0]=fma2(a2,b0,acc[2][0]); acc[2][1]=fma2(a2,b1,acc[2][1]);
            acc[2][2]=fma2(a2,b2,acc[2][2]); acc[2][3]=fma2(a2,b3,acc[2][3]);
            acc[3][0]=fma2(a3,b0,acc[3][0]); acc[3][1]=fma2(a3,b1,acc[3][1]);
            acc[3][2]=fma2(a3,b2,acc[3][2]); acc[3][3]=fma2(a3,b3,acc[3][3]);
        }
        __syncthreads();
    }
    float4 bb = *(const float4*)&bias[n0 + tx*4];
    #pragma unroll
    for (int p = 0; p < 4; p++){
        float2 v0=u2f(acc[p][0]), v1=u2f(acc[p][1]), v2=u2f(acc[p][2]), v3=u2f(acc[p][3]);
        float4 o0, o1;
        o0.x=v0.x+bb.x; o0.y=v1.x+bb.y; o0.z=v2.x+bb.z; o0.w=v3.x+bb.w;
        o1.x=v0.y+bb.x; o1.y=v1.y+bb.y; o1.z=v2.y+bb.z; o1.w=v3.y+bb.w;
        if (RELU){
            o0.x=fmaxf(o0.x,0.f); o0.y=fmaxf(o0.y,0.f); o0.z=fmaxf(o0.z,0.f); o0.w=fmaxf(o0.w,0.f);
            o1.x=fmaxf(o1.x,0.f); o1.y=fmaxf(o1.y,0.f); o1.z=fmaxf(o1.z,0.f); o1.w=fmaxf(o1.w,0.f);
        }
        int r0 = m0 + ty*8 + p*2;
        *(float4*)&C[(size_t)r0*ldc     + n0 + tx*4] = o0;
        *(float4*)&C[(size_t)(r0+1)*ldc + n0 + tx*4] = o1;
    }
}

__global__ void gather_xin(const float* __restrict__ values,
                           const int* __restrict__ actions, const int* __restrict__ a0)
{
    int idx = blockIdx.x * blockDim.x + threadIdx.x;
    if (idx >= T_*N_*80) return;
    int i = idx / 80, c4 = idx % 80;
    float4 f;
    if (c4 < 16) f = *(const float4*)&values[(size_t)i*64 + c4*4];
    else {
        int t = i >> 8, n = i & 255;
        int ap = (t == 0) ? a0[n] : actions[i - 256];
        f = *(const float4*)&d_M[((size_t)n*64 + ap)*256 + (c4-16)*4];
    }
    *(float4*)&d_Xin[(size_t)i*320 + c4*4] = f;
}

// ---------------- qg_W transpose + c vector -------------------------------------
__global__ void transpose_qgw(const float* __restrict__ qg_W)
{
    int idx = blockIdx.x*256 + threadIdx.x;
    int k = idx >> 8, j = idx & 255;
    d_Wt[idx] = qg_W[j*512 + k];
}

__global__ void calc_cvec(const float* __restrict__ qg_b)
{
    int row = blockIdx.x*8 + (threadIdx.x >> 5);
    int lane = threadIdx.x & 31;
    const float* kr = d_K + (size_t)row*512;
    float s = 0.f;
    #pragma unroll
    for (int j = 0; j < 16; j++){ int k = lane + j*32; s += kr[k]*qg_b[k]; }
    #pragma unroll
    for (int o = 16; o > 0; o >>= 1) s += __shfl_xor_sync(0xffffffffu, s, o);
    if (lane == 0) d_cv[row] = s;
}

// ===== persistent cell chain + GIc gating + H-progress publishing ================
__global__ void __launch_bounds__(256,1) cell_chain(
    const float* GIc, const float* __restrict__ h0,
    const float* __restrict__ Whh, const float* __restrict__ bhh, float* __restrict__ H)
{
    extern __shared__ char sm[];
    U64*   WsA = (U64*)sm;
    U64*   WsB = (U64*)(sm + 65536);
    float* Hs  = (float*)(sm + 98304);
    U64*   Rs  = (U64*)(sm + 131072);
    const int tid = threadIdx.x;
    const int kg = tid >> 7, q = tid & 127;
    const int col  = (q & 7) + ((q >> 6) & 1) * 8;
    const int slot = (q >> 3) & 7;
    const int grp = blockIdx.x >> 4;
    const int rb = grp * 32, hcB = (blockIdx.x & 15) * 16, hcol = hcB + col;
    const int nb = rb + 4*slot;

    for (int i = tid; i < 256*32; i += 256){
        int k = i >> 5, cc = i & 31, c = cc >> 1, g = cc & 1;
        WsA[i] = pack_dup(Whh[(size_t)k*768 + g*256 + hcB + c]);
    }
    for (int i = tid; i < 256*16; i += 256){
        int k = i >> 4, c = i & 15;
        WsB[i] = pack_dup(Whh[(size_t)k*768 + 512 + hcB + c]);
    }
    const float brv = bhh[hcol], bzv = bhh[256+hcol], bnv = bhh[512+hcol];
    __syncthreads();

    if (tid == 0){ while (*(volatile unsigned*)&d_prog < 1u) { } __threadfence(); }
    __syncthreads();

    float gR[4], gZ[4], gN[4];
    if (kg == 0){
        #pragma unroll
        for (int j = 0; j < 4; j++){
            const float* gi = GIc + (size_t)(nb+j)*768;
            gR[j] = ldcg(gi + hcol); gZ[j] = ldcg(gi + 256 + hcol); gN[j] = ldcg(gi + 512 + hcol);
        }
    }

    for (int t = 0; t < T_; t++){
        if (t == 0){
            for (int i = tid; i < 2048; i += 256){
                int r = i >> 6, c4 = i & 63;
                float4 f = *(const float4*)&h0[(size_t)(rb+r)*256 + c4*4];
                Hs[(c4*4+0)*32+r]=f.x; Hs[(c4*4+1)*32+r]=f.y;
                Hs[(c4*4+2)*32+r]=f.z; Hs[(c4*4+3)*32+r]=f.w;
            }
        } else {
            const float* hp = d_Ht + (size_t)(t-1)*65536;
            for (int i = tid; i < 2048; i += 256){
                int c = i >> 3, rg = i & 7;
                float4 f = *(const float4*)&hp[(size_t)c*256 + rb + rg*4];
                *(float4*)&Hs[c*32 + rg*4] = f;
            }
        }
        __syncthreads();

        U64 acc[2][3];
        acc[0][0]=acc[0][1]=acc[0][2]=0ull; acc[1][0]=acc[1][1]=acc[1][2]=0ull;
        {
            const int kbase = kg << 7;
            #pragma unroll 8
            for (int k = 0; k < 128; k++){
                int kk = kbase + k;
                ulonglong2 av = *(const ulonglong2*)&Hs[kk*32 + 4*slot];
                ulonglong2 brz = *(const ulonglong2*)&WsA[kk*32 + col*2];
                U64 bn = WsB[kk*16 + col];
                acc[0][0]=fma2(av.x,brz.x,acc[0][0]);
                acc[0][1]=fma2(av.x,brz.y,acc[0][1]);
                acc[0][2]=fma2(av.x,bn,   acc[0][2]);
                acc[1][0]=fma2(av.y,brz.x,acc[1][0]);
                acc[1][1]=fma2(av.y,brz.y,acc[1][1]);
                acc[1][2]=fma2(av.y,bn,   acc[1][2]);
            }
        }
        if (kg == 1){
            U64* r = Rs + q*6;
            r[0]=acc[0][0]; r[1]=acc[0][1]; r[2]=acc[0][2];
            r[3]=acc[1][0]; r[4]=acc[1][1]; r[5]=acc[1][2];
        }
        __syncthreads();
        if (kg == 0){
            const U64* r = Rs + q*6;
            float vals[4];
            #pragma unroll
            for (int i = 0; i < 2; i++){
                float2 gr = u2f(add2(acc[i][0], r[i*3+0]));
                float2 gz = u2f(add2(acc[i][1], r[i*3+1]));
                float2 gn = u2f(add2(acc[i][2], r[i*3+2]));
                #pragma unroll
                for (int rr = 0; rr < 2; rr++){
                    int j = 2*i + rr;
                    int rl = 4*slot + j;
                    float ghr = rr ? gr.y : gr.x;
                    float ghz = rr ? gz.y : gz.x;
                    float ghn = rr ? gn.y : gn.x;
                    float hpv = Hs[hcol*32 + rl];
                    float r_ = sigm(gR[j] + ghr + brv);
                    float z_ = sigm(gZ[j] + ghz + bzv);
                    float n_ = tanhf(gN[j] + r_*(ghn + bnv));
                    vals[j] = (1.f - z_)*n_ + z_*hpv;
                    H[(size_t)t*65536 + (nb+j)*256 + hcol] = vals[j];
                }
            }
            *(float4*)&d_Ht[(size_t)t*65536 + hcol*256 + nb] =
                make_float4(vals[0], vals[1], vals[2], vals[3]);
        }
        if (t+1 < T_){
            const int tn = t+1;
            const bool bd = (tn & 63) == 0;
            if (kg == 0 && !bd){
                #pragma unroll
                for (int j = 0; j < 4; j++){
                    const float* gi = GIc + ((size_t)tn*256 + nb + j)*768;
                    gR[j] = ldcg(gi + hcol); gZ[j] = ldcg(gi + 256 + hcol); gN[j] = ldcg(gi + 512 + hcol);
                }
            }
            __threadfence();
            __syncthreads();
            if (tid == 0){
                if ((tn & 127) == 0) atomicAdd(&d_progH, 1u);
                atomicAdd(&d_barC[grp*32], 1u);
                unsigned tg = 16u*tn;
                while (*(volatile unsigned*)&d_barC[grp*32] < tg) { }
                if (bd){
                    unsigned need = (unsigned)(tn >> 6) + 1u;
                    while (*(volatile unsigned*)&d_prog < need) { }
                }
                __threadfence();
            }
            __syncthreads();
            if (kg == 0 && bd){
                #pragma unroll
                for (int j = 0; j < 4; j++){
                    const float* gi = GIc + ((size_t)tn*256 + nb + j)*768;
                    gR[j] = ldcg(gi + hcol); gZ[j] = ldcg(gi + 256 + hcol); gN[j] = ldcg(gi + 512 + hcol);
                }
            }
        }
    }
    __threadfence();
    __syncthreads();
    if (tid == 0) atomicAdd(&d_progH, 1u);
}

// ===== persistent encoder chain (R9-proven) ======================================
__global__ void __launch_bounds__(256,1) enc_chain(
    const float* __restrict__ GIf, const float* __restrict__ GIb,
    const float* __restrict__ Wf,  const float* __restrict__ Wb,
    const float* __restrict__ bf,  const float* __restrict__ bb,
    float* __restrict__ Kout)
{
    extern __shared__ char sm[];
    U64*   Ws = (U64*)sm;
    float* Hs = (float*)(sm + 98304);
    const int tid = threadIdx.x;
    const int w = tid >> 5, l = tid & 31;
    const int colL = ((w & 1) << 3) + (l >> 2);
    const int r4   = ((w >> 1) << 2) + (l & 3);
    const int dir = blockIdx.x >> 6, b6 = blockIdx.x & 63;
    const int rbi = b6 >> 4, grp = dir*4 + rbi;
    const int rb = rbi*64, hcB = (b6 & 15)*16, hcol = hcB + colL;
    const float* W  = dir ? Wb  : Wf;
    const float* bh = dir ? bb  : bf;
    const float* GI = dir ? GIb : GIf;
    float* Kt = d_Kt + (size_t)dir*HR_*65536;
    for (int i = tid; i < 256*48; i += 256){
        int k = i/48, cc = i%48, g = cc>>4, c = cc&15;
        Ws[i] = pack_dup(W[(size_t)k*768 + g*256 + hcB + c]);
    }
    const float brv = bh[hcol], bzv = bh[256+hcol], bnv = bh[512+hcol];
    __syncthreads();
    for (int step = 0; step < HR_; step++){
        const int s = dir ? (HR_-1-step) : step;
        if (step == 0){
            for (int i = tid; i < 4096; i += 256)
                *(float4*)&Hs[i*4] = make_float4(0.f,0.f,0.f,0.f);
        } else {
            const int sp = dir ? (s+1) : (s-1);
            const float* hp = Kt + (size_t)sp*65536;
            for (int i = tid; i < 4096; i += 256){
                int c = i >> 4, rg = i & 15;
                float4 f = *(const float4*)&hp[(size_t)c*256 + rb + rg*4];
                *(float4*)&Hs[c*64 + rg*4] = f;
            }
        }
        __syncthreads();
        float gpr[4], gpz[4], gpn[4];
        #pragma unroll
        for (int i = 0; i < 4; i++){
            int n = rb + 4*r4 + i;
            const float* gi = GI + (size_t)(n*64 + s)*768;
            gpr[i] = gi[hcol]; gpz[i] = gi[256+hcol]; gpn[i] = gi[512+hcol];
        }
        U64 acc[2][3]; acc[0][0]=acc[0][1]=acc[0][2]=0ull; acc[1][0]=acc[1][1]=acc[1][2]=0ull;
        const U64* HsU = (const U64*)Hs;
        #pragma unroll 8
        for (int k = 0; k < 256; k++){
            U64 a0 = HsU[k*32 + 2*r4], a1 = HsU[k*32 + 2*r4 + 1];
            U64 b0 = Ws[k*48 + colL], b1 = Ws[k*48 + 16+colL], b2 = Ws[k*48 + 32+colL];
            acc[0][0]=fma2(a0,b0,acc[0][0]); acc[0][1]=fma2(a0,b1,acc[0][1]); acc[0][2]=fma2(a0,b2,acc[0][2]);
            acc[1][0]=fma2(a1,b0,acc[1][0]); acc[1][1]=fma2(a1,b1,acc[1][1]); acc[1][2]=fma2(a1,b2,acc[1][2]);
        }
        float vals[4];
        #pragma unroll
        for (int i = 0; i < 2; i++){
            float2 gr = u2f(acc[i][0]), gz = u2f(acc[i][1]), gn = u2f(acc[i][2]);
            #pragma unroll
            for (int rr = 0; rr < 2; rr++){
                int j = 2*i + rr;
                int rl = 4*r4 + j, n = rb + rl;
                float ghr = rr ? gr.y : gr.x, ghz = rr ? gz.y : gz.x, ghn = rr ? gn.y : gn.x;
                float hpv = Hs[hcol*64 + rl];
                float r_ = sigm(gpr[j] + ghr + brv);
                float z_ = sigm(gpz[j] + ghz + bzv);
                float n_ = tanhf(gpn[j] + r_*(ghn + bnv));
                vals[j] = (1.f - z_)*n_ + z_*hpv;
                Kout[(size_t)(n*64 + s)*512 + dir*256 + hcol] = vals[j];
            }
        }
        *(float4*)&Kt[(size_t)s*65536 + hcol*256 + rb + 4*r4] =
            make_float4(vals[0], vals[1], vals[2], vals[3]);
        if (step+1 < HR_){
            __threadfence();
            __syncthreads();
            if (tid == 0){
                atomicAdd(&d_barE[grp*32], 1u);
                unsigned tg = 16u*(step+1);
                while (*(volatile unsigned*)&d_barE[grp*32] < tg) { }
                __threadfence();
            }
            __syncthreads();
        }
    }
}

// ------ logits v2, chunked & gated on H progress: 128 timesteps per launch ------
__global__ void __launch_bounds__(256) logits_gemm2(int chunk)
{
    if (threadIdx.x == 0){
        unsigned need = 128u*(unsigned)(chunk+1);
        while (*(volatile unsigned*)&d_progH < need) __nanosleep(200);
    }
    __syncthreads();
    const int n  = blockIdx.y, m0 = chunk * 128;
    const float* Aq = d_H + (size_t)n*256;
    const float* Gn = d_G + (size_t)n*16384;
    __shared__ __align__(16) float As[16][128];
    __shared__ __align__(16) float Bs[16][64];
    const int tid = threadIdx.x, tx = tid & 15, ty = tid >> 4;
    U64 acc[4][4] = {};
    for (int k0 = 0; k0 < 256; k0 += 16){
        #pragma unroll
        for (int l = 0; l < 2; l++){
            int q = tid + l*256, row = q >> 2, c4 = q & 3;
            float4 f = ldcg4(&Aq[(size_t)(m0+row)*65536 + k0 + c4*4]);
            As[c4*4+0][row]=f.x; As[c4*4+1][row]=f.y; As[c4*4+2][row]=f.z; As[c4*4+3][row]=f.w;
        }
        {
            int srow = tid >> 2, c4 = tid & 3;
            float4 f = *(const float4*)&Gn[(size_t)srow*256 + k0 + c4*4];
            Bs[c4*4+0][srow]=f.x; Bs[c4*4+1][srow]=f.y; Bs[c4*4+2][srow]=f.z; Bs[c4*4+3][srow]=f.w;
        }
        __syncthreads();
        #pragma unroll
        for (int k = 0; k < 16; k++){
            const U64* ap = (const U64*)&As[k][ty*8];
            U64 a0=ap[0], a1=ap[1], a2=ap[2], a3=ap[3];
            float4 bv = *(const float4*)&Bs[k][tx*4];
            U64 b0=pack_dup(bv.x), b1=pack_dup(bv.y), b2=pack_dup(bv.z), b3=pack_dup(bv.w);
            acc[0][0]=fma2(a0,b0,acc[0][0]); acc[0][1]=fma2(a0,b1,acc[0][1]);
            acc[0][2]=fma2(a0,b2,acc[0][2]); acc[0][3]=fma2(a0,b3,acc[0][3]);
            acc[1][0]=fma2(a1,b0,acc[1][0]); acc[1][1]=fma2(a1,b1,acc[1][1]);
            acc[1][2]=fma2(a1,b2,acc[1][2]); acc[1][3]=fma2(a1,b3,acc[1][3]);
            acc[2][0]=fma2(a2,b0,acc[2][0]); acc[2][1]=fma2(a2,b1,acc[2][1]);
            acc[2][2]=fma2(a2,b2,acc[2][2]); acc[2][3]=fma2(a2,b3,acc[2][3]);
            acc[3][0]=fma2(a3,b0,acc[3][0]); acc[3][1]=fma2(a3,b1,acc[3][1]);
            acc[3][2]=fma2(a3,b2,acc[3][2]); acc[3][3]=fma2(a3,b3,acc[3][3]);
        }
        __syncthreads();
    }
    float4 cc = *(const float4*)&d_cv[n*64 + tx*4];
    float cj[4] = {cc.x, cc.y, cc.z, cc.w};
    #pragma unroll
    for (int p = 0; p < 4; p++){
        int t0 = m0 + ty*8 + p*2;
        #pragma unroll
        for (int j = 0; j < 4; j++){
            float2 v = u2f(acc[p][j]);
            d_Lg[((size_t)t0*256 + n)*64 + tx*4 + j]     = v.x + cj[j];
            d_Lg[((size_t)(t0+1)*256 + n)*64 + tx*4 + j] = v.y + cj[j];
        }
    }
}

__global__ void __launch_bounds__(256) pack_out(
    int wbase,
    const int* __restrict__ actions,
    const float* __restrict__ critic_W, const float* __restrict__ critic_b,
    float* __restrict__ out)
{
    int wid = wbase + blockIdx.x*8 + (threadIdx.x >> 5), lane = threadIdx.x & 31;
    const float* h  = d_H  + (size_t)wid*256;
    const float* lg = d_Lg + (size_t)wid*64;
    float* o = out + (size_t)wid*322;
    float c = 0.f;
    #pragma unroll
    for (int j = 0; j < 8; j++){ int k = lane + j*32; c += h[k]*critic_W[k]; }
    #pragma unroll
    for (int s = 16; s > 0; s >>= 1) c += __shfl_xor_sync(0xffffffffu, c, s);
    #pragma unroll
    for (int j = 0; j < 8; j++){ int k = lane + j*32; o[2 + k] = h[k]; }
    float x0 = lg[lane], x1 = lg[lane + 32];
    float m = fmaxf(x0, x1);
    #pragma unroll
    for (int s = 16; s > 0; s >>= 1) m = fmaxf(m, __shfl_xor_sync(0xffffffffu, m, s));
    float e0 = expf(x0 - m), e1 = expf(x1 - m);
    float ssum = e0 + e1;
    #pragma unroll
    for (int s = 16; s > 0; s >>= 1) ssum += __shfl_xor_sync(0xffffffffu, ssum, s);
    float inv = 1.f / ssum;
    o[258 + lane] = e0 * inv;
    o[290 + lane] = e1 * inv;
    if (lane == 0){ o[0] = (float)actions[wid]; o[1] = c + critic_b[0]; }
}

extern "C" void kernel_launch(void* const* d_in, const int* in_sizes, int n_in,
                              void* d_out, int out_size)
{
    const float* values   = (const float*)d_in[0];
    const float* mdp      = (const float*)d_in[1];
    const int*   actions  = (const int*)  d_in[2];
    const int*   a0       = (const int*)  d_in[3];
    const float* h0       = (const float*)d_in[4];
    const float* emb_W    = (const float*)d_in[5];
    const float* emb_b    = (const float*)d_in[6];
    const float* gfw_Wih  = (const float*)d_in[7];
    const float* gfw_Whh  = (const float*)d_in[8];
    const float* gfw_bih  = (const float*)d_in[9];
    const float* gfw_bhh  = (const float*)d_in[10];
    const float* gbw_Wih  = (const float*)d_in[11];
    const float* gbw_Whh  = (const float*)d_in[12];
    const float* gbw_bih  = (const float*)d_in[13];
    const float* gbw_bhh  = (const float*)d_in[14];
    const float* f0_W     = (const float*)d_in[15];
    const float* f0_b     = (const float*)d_in[16];
    const float* f1_W     = (const float*)d_in[17];
    const float* f1_b     = (const float*)d_in[18];
    const float* cell_Wih = (const float*)d_in[19];
    const float* cell_Whh = (const float*)d_in[20];
    const float* cell_bih = (const float*)d_in[21];
    const float* cell_bhh = (const float*)d_in[22];
    const float* critic_W = (const float*)d_in[23];
    const float* critic_b = (const float*)d_in[24];
    const float* qg_W     = (const float*)d_in[25];
    const float* qg_b     = (const float*)d_in[26];
    float* out = (float*)d_out;

    float *pM, *pGIf, *pGIb, *pK, *pXin, *pX0, *pX1, *pGIc, *pH, *pG, *pWt, *pZ;
    cudaGetSymbolAddress((void**)&pM,   d_M);
    cudaGetSymbolAddress((void**)&pGIf, d_GIf);
    cudaGetSymbolAddress((void**)&pGIb, d_GIb);
    cudaGetSymbolAddress((void**)&pK,   d_K);
    cudaGetSymbolAddress((void**)&pXin, d_Xin);
    cudaGetSymbolAddress((void**)&pX0,  d_X0);
    cudaGetSymbolAddress((void**)&pX1,  d_X1);
    cudaGetSymbolAddress((void**)&pGIc, d_GIc);
    cudaGetSymbolAddress((void**)&pH,   d_H);
    cudaGetSymbolAddress((void**)&pG,   d_G);
    cudaGetSymbolAddress((void**)&pWt,  d_Wt);
    cudaGetSymbolAddress((void**)&pZ,   d_Z);

    cudaFuncSetAttribute(enc_chain,  cudaFuncAttributeMaxDynamicSharedMemorySize, 163840);
    cudaFuncSetAttribute(cell_chain, cudaFuncAttributeMaxDynamicSharedMemorySize, 163840);

    static cudaStream_t sB = 0;
    static cudaEvent_t evG = 0, evEnc = 0, evTail = 0;
    if (!sB){
        cudaStreamCreateWithFlags(&sB, cudaStreamNonBlocking);
        cudaEventCreateWithFlags(&evG,    cudaEventDisableTiming);
        cudaEventCreateWithFlags(&evEnc,  cudaEventDisableTiming);
        cudaEventCreateWithFlags(&evTail, cudaEventDisableTiming);
    }

    // ---- stream 0: pre, enc, then the persistent cell chain --------------------
    zero_bars<<<1,256>>>();
    gemm_nn<false><<<dim3(4,128), 256>>>(mdp, 128, emb_W, 256, emb_b, pM, 256, 128);
    gemm_nn<false><<<dim3(12,128), 256>>>(pM, 256, gfw_Wih, 768, gfw_bih, pGIf, 768, 256);
    gemm_nn<false><<<dim3(12,128), 256>>>(pM, 256, gbw_Wih, 768, gbw_bih, pGIb, 768, 256);
    gather_xin<<<(T_*N_*80 + 255)/256, 256>>>(values, actions, a0);
    cudaEventRecord(evG, 0);
    enc_chain<<<128, 256, 163840>>>(pGIf, pGIb, gfw_Whh, gbw_Whh, gfw_bhh, gbw_bhh, pK);
    cudaEventRecord(evEnc, 0);
    cell_chain<<<128, 256, 137280>>>(pGIc, h0, cell_Whh, cell_bhh, pH);

    // ---- sB: producer (f0/f1 under enc; GIc chunks under cell), then tail ------
    cudaStreamWaitEvent(sB, evG, 0);
    gemm_nn<true ><<<dim3(4,1024), 256, 0, sB>>>(pXin, 320, f0_W, 256, f0_b, pX0, 256, 320);
    gemm_nn<true ><<<dim3(4,1024), 256, 0, sB>>>(pX0, 256, f1_W, 256, f1_b, pX1, 256, 256);
    for (int c = 0; c < 8; c++){
        const size_t r0 = (size_t)c*16384;
        gemm_nn<false><<<dim3(12,128), 256, 0, sB>>>(
            pX1 + r0*256, 256, cell_Wih, 768, cell_bih, pGIc + r0*768, 768, 256);
        set_prog<<<1,1,0,sB>>>((unsigned)(c+1));
    }
    cudaStreamWaitEvent(sB, evEnc, 0);
    transpose_qgw<<<512, 256, 0, sB>>>(qg_W);
    calc_cvec<<<2048, 256, 0, sB>>>(qg_b);
    gemm_nn<false><<<dim3(4,128), 256, 0, sB>>>(pK, 512, pWt, 256, pZ, pG, 256, 512);
    for (int c = 0; c < 4; c++){
        logits_gemm2<<<dim3(1,256), 256, 0, sB>>>(c);
        pack_out<<<4096, 256, 0, sB>>>(c*32768, actions, critic_W, critic_b, out);
    }
    cudaEventRecord(evTail, sB);

    // join sB into stream 0
    cudaStreamWaitEvent(0, evTail, 0);
}

// round 17
// speedup vs baseline: 1.1278x; 1.1278x over previous
#include <cuda_runtime.h>
#include <math.h>

#define T_  512
#define N_  256
#define H_  256
#define HR_ 64
#define V_  64

typedef unsigned long long U64;

__device__ __forceinline__ U64 pack_dup(float x){ U64 r; asm("mov.b64 %0, {%1, %1};" : "=l"(r) : "f"(x)); return r; }
__device__ __forceinline__ U64 fma2(U64 a, U64 b, U64 c){ U64 d; asm("fma.rn.f32x2 %0, %1, %2, %3;" : "=l"(d) : "l"(a), "l"(b), "l"(c)); return d; }
__device__ __forceinline__ U64 add2(U64 a, U64 b){ U64 d; asm("add.rn.f32x2 %0, %1, %2;" : "=l"(d) : "l"(a), "l"(b)); return d; }
__device__ __forceinline__ float2 u2f(U64 v){ float2 f; asm("mov.b64 {%0, %1}, %2;" : "=f"(f.x), "=f"(f.y) : "l"(v)); return f; }
__device__ __forceinline__ float sigm(float x){ return 1.f / (1.f + expf(-x)); }
// L2-coherent loads — REQUIRED for data produced by a concurrently-running kernel
__device__ __forceinline__ float ldcg(const float* p){
    float v; asm volatile("ld.global.cg.f32 %0, [%1];" : "=f"(v) : "l"(p)); return v;
}
__device__ __forceinline__ float4 ldcg4(const float* p){
    float4 v; asm volatile("ld.global.cg.v4.f32 {%0,%1,%2,%3}, [%4];"
        : "=f"(v.x), "=f"(v.y), "=f"(v.z), "=f"(v.w) : "l"(p)); return v;
}

__device__ float d_M  [N_*HR_*H_];
__device__ float d_GIf[N_*HR_*3*H_];
__device__ float d_GIb[N_*HR_*3*H_];
__device__ float d_K  [N_*HR_*2*H_];
__device__ float d_Xin[T_*N_*(V_+H_)];
__device__ float d_X0 [T_*N_*H_];
__device__ float d_X1 [T_*N_*H_];
__device__ float d_GIc[T_*N_*3*H_];
__device__ float d_H  [T_*N_*H_];
__device__ float d_Ht [T_*N_*H_];          // [t][col][n]
__device__ float d_Kt [2*HR_*N_*H_];       // [dir][s][col][n]
__device__ float d_G  [N_*HR_*H_];         // [n][s][j]  = K[n,s,:]@qg_W^T
__device__ float d_Wt [2*H_*H_];           // qg_W^T (512,256)
__device__ float d_cv [N_*HR_];            // c[n,s] = qg_b . K[n,s,:]
__device__ float d_Lg [T_*N_*HR_];
__device__ float d_Z  [H_];                // zeros (never written)
__device__ unsigned d_barE[8*32], d_barC[8*32];
__device__ unsigned d_prog;                // GIc chunks completed (0..8)
__device__ unsigned d_progH;               // H 128-step blocks completed (0..4), 128 arrivals each

__global__ void zero_bars(){
    if (threadIdx.x < 256) d_barE[threadIdx.x] = 0u;
    if (threadIdx.x < 256) d_barC[threadIdx.x] = 0u;
    if (threadIdx.x == 0){ d_prog = 0u; d_progH = 0u; }
}

__global__ void set_prog(unsigned v){ d_prog = v; }

// ---------------- fp32 GEMM (FFMA2), tile 128x64  (proven — DO NOT TOUCH) -------
template<bool RELU>
__global__ void __launch_bounds__(256) gemm_nn(
    const float* __restrict__ A, int lda, const float* __restrict__ B, int ldb,
    const float* __restrict__ bias, float* __restrict__ C, int ldc, int Kd)
{
    __shared__ __align__(16) float As[16][128];
    __shared__ __align__(16) float Bs[16][64];
    const int m0 = blockIdx.y * 128, n0 = blockIdx.x * 64;
    const int tid = threadIdx.x, tx = tid & 15, ty = tid >> 4;
    U64 acc[4][4] = {};
    for (int k0 = 0; k0 < Kd; k0 += 16){
        #pragma unroll
        for (int l = 0; l < 2; l++){
            int q = tid + l*256, row = q >> 2, c4 = q & 3;
            float4 f = *(const float4*)&A[(size_t)(m0+row)*lda + k0 + c4*4];
            As[c4*4+0][row] = f.x; As[c4*4+1][row] = f.y;
            As[c4*4+2][row] = f.z; As[c4*4+3][row] = f.w;
        }
        {
            int kr = tid >> 4, c4 = tid & 15;
            *(float4*)&Bs[kr][c4*4] = *(const float4*)&B[(size_t)(k0+kr)*ldb + n0 + c4*4];
        }
        __syncthreads();
        #pragma unroll
        for (int k = 0; k < 16; k++){
            const U64* ap = (const U64*)&As[k][ty*8];
            U64 a0 = ap[0], a1 = ap[1], a2 = ap[2], a3 = ap[3];
            float4 bv = *(const float4*)&Bs[k][tx*4];
            U64 b0 = pack_dup(bv.x), b1 = pack_dup(bv.y);
            U64 b2 = pack_dup(bv.z), b3 = pack_dup(bv.w);
            acc[0][0]=fma2(a0,b0,acc[0][0]); acc[0][1]=fma2(a0,b1,acc[0][1]);
            acc[0][2]=fma2(a0,b2,acc[0][2]); acc[0][3]=fma2(a0,b3,acc[0][3]);
            acc[1][0]=fma2(a1,b0,acc[1][0]); acc[1][1]=fma2(a1,b1,acc[1][1]);
            acc[1][2]=fma2(a1,b2,acc[1][2]); acc[1][3]=fma2(a1,b3,acc[1][3]);
            acc[2][0]=fma2(a2,b0,acc[2][0]); acc[2][1]=fma2(a2,b1,acc[2][1]);
            acc[2][2]=fma2(a2,b2,acc[2][2]); acc[2][3]=fma2(a2,b3,acc[2][3]);
            acc[3][0]=fma2(a3,b0,acc[3][0]); acc[3][1]=fma2(a3,b1,acc[3][1]);
            acc[3][2]=fma2(a3,b2,acc[3][2]); acc[3][3]=fma2(a3,b3,acc[3][3]);
        }
        __syncthreads();
    }
    float4 bb = *(const float4*)&bias[n0 + tx*4];
    #pragma unroll
    for (int p = 0; p < 4; p++){
        float2 v0=u2f(acc[p][0]), v1=u2f(acc[p][1]), v2=u2f(acc[p][2]), v3=u2f(acc[p][3]);
        float4 o0, o1;
        o0.x=v0.x+bb.x; o0.y=v1.x+bb.y; o0.z=v2.x+bb.z; o0.w=v3.x+bb.w;
        o1.x=v0.y+bb.x; o1.y=v1.y+bb.y; o1.z=v2.y+bb.z; o1.w=v3.y+bb.w;
        if (RELU){
            o0.x=fmaxf(o0.x,0.f); o0.y=fmaxf(o0.y,0.f); o0.z=fmaxf(o0.z,0.f); o0.w=fmaxf(o0.w,0.f);
            o1.x=fmaxf(o1.x,0.f); o1.y=fmaxf(o1.y,0.f); o1.z=fmaxf(o1.z,0.f); o1.w=fmaxf(o1.w,0.f);
        }
        int r0 = m0 + ty*8 + p*2;
        *(float4*)&C[(size_t)r0*ldc     + n0 + tx*4] = o0;
        *(float4*)&C[(size_t)(r0+1)*ldc + n0 + tx*4] = o1;
    }
}

__global__ void gather_xin(const float* __restrict__ values,
                           const int* __restrict__ actions, const int* __restrict__ a0)
{
    int idx = blockIdx.x * blockDim.x + threadIdx.x;
    if (idx >= T_*N_*80) return;
    int i = idx / 80, c4 = idx % 80;
    float4 f;
    if (c4 < 16) f = *(const float4*)&values[(size_t)i*64 + c4*4];
    else {
        int t = i >> 8, n = i & 255;
        int ap = (t == 0) ? a0[n] : actions[i - 256];
        f = ldcg4(&d_M[((size_t)n*64 + ap)*256 + (c4-16)*4]);   // M from concurrent producer-safe path
    }
    *(float4*)&d_Xin[(size_t)i*320 + c4*4] = f;
}

// ---------------- qg_W transpose + c vector -------------------------------------
__global__ void transpose_qgw(const float* __restrict__ qg_W)
{
    int idx = blockIdx.x*256 + threadIdx.x;
    int k = idx >> 8, j = idx & 255;
    d_Wt[idx] = qg_W[j*512 + k];
}

__global__ void calc_cvec(const float* __restrict__ qg_b)
{
    int row = blockIdx.x*8 + (threadIdx.x >> 5);
    int lane = threadIdx.x & 31;
    const float* kr = d_K + (size_t)row*512;
    float s = 0.f;
    #pragma unroll
    for (int j = 0; j < 16; j++){ int k = lane + j*32; s += kr[k]*qg_b[k]; }
    #pragma unroll
    for (int o = 16; o > 0; o >>= 1) s += __shfl_xor_sync(0xffffffffu, s, o);
    if (lane == 0) d_cv[row] = s;
}

// ===== persistent cell chain + GIc gating + H-progress publishing ================
__global__ void __launch_bounds__(256,1) cell_chain(
    const float* GIc, const float* __restrict__ h0,
    const float* __restrict__ Whh, const float* __restrict__ bhh, float* __restrict__ H)
{
    extern __shared__ char sm[];
    U64*   WsA = (U64*)sm;
    U64*   WsB = (U64*)(sm + 65536);
    float* Hs  = (float*)(sm + 98304);
    U64*   Rs  = (U64*)(sm + 131072);
    const int tid = threadIdx.x;
    const int kg = tid >> 7, q = tid & 127;
    const int col  = (q & 7) + ((q >> 6) & 1) * 8;
    const int slot = (q >> 3) & 7;
    const int grp = blockIdx.x >> 4;
    const int rb = grp * 32, hcB = (blockIdx.x & 15) * 16, hcol = hcB + col;
    const int nb = rb + 4*slot;

    for (int i = tid; i < 256*32; i += 256){
        int k = i >> 5, cc = i & 31, c = cc >> 1, g = cc & 1;
        WsA[i] = pack_dup(Whh[(size_t)k*768 + g*256 + hcB + c]);
    }
    for (int i = tid; i < 256*16; i += 256){
        int k = i >> 4, c = i & 15;
        WsB[i] = pack_dup(Whh[(size_t)k*768 + 512 + hcB + c]);
    }
    const float brv = bhh[hcol], bzv = bhh[256+hcol], bnv = bhh[512+hcol];
    __syncthreads();

    if (tid == 0){ while (*(volatile unsigned*)&d_prog < 1u) { } __threadfence(); }
    __syncthreads();

    float gR[4], gZ[4], gN[4];
    if (kg == 0){
        #pragma unroll
        for (int j = 0; j < 4; j++){
            const float* gi = GIc + (size_t)(nb+j)*768;
            gR[j] = ldcg(gi + hcol); gZ[j] = ldcg(gi + 256 + hcol); gN[j] = ldcg(gi + 512 + hcol);
        }
    }

    for (int t = 0; t < T_; t++){
        if (t == 0){
            for (int i = tid; i < 2048; i += 256){
                int r = i >> 6, c4 = i & 63;
                float4 f = *(const float4*)&h0[(size_t)(rb+r)*256 + c4*4];
                Hs[(c4*4+0)*32+r]=f.x; Hs[(c4*4+1)*32+r]=f.y;
                Hs[(c4*4+2)*32+r]=f.z; Hs[(c4*4+3)*32+r]=f.w;
            }
        } else {
            const float* hp = d_Ht + (size_t)(t-1)*65536;
            for (int i = tid; i < 2048; i += 256){
                int c = i >> 3, rg = i & 7;
                float4 f = *(const float4*)&hp[(size_t)c*256 + rb + rg*4];
                *(float4*)&Hs[c*32 + rg*4] = f;
            }
        }
        __syncthreads();

        U64 acc[2][3];
        acc[0][0]=acc[0][1]=acc[0][2]=0ull; acc[1][0]=acc[1][1]=acc[1][2]=0ull;
        {
            const int kbase = kg << 7;
            #pragma unroll 8
            for (int k = 0; k < 128; k++){
                int kk = kbase + k;
                ulonglong2 av = *(const ulonglong2*)&Hs[kk*32 + 4*slot];
                ulonglong2 brz = *(const ulonglong2*)&WsA[kk*32 + col*2];
                U64 bn = WsB[kk*16 + col];
                acc[0][0]=fma2(av.x,brz.x,acc[0][0]);
                acc[0][1]=fma2(av.x,brz.y,acc[0][1]);
                acc[0][2]=fma2(av.x,bn,   acc[0][2]);
                acc[1][0]=fma2(av.y,brz.x,acc[1][0]);
                acc[1][1]=fma2(av.y,brz.y,acc[1][1]);
                acc[1][2]=fma2(av.y,bn,   acc[1][2]);
            }
        }
        if (kg == 1){
            U64* r = Rs + q*6;
            r[0]=acc[0][0]; r[1]=acc[0][1]; r[2]=acc[0][2];
            r[3]=acc[1][0]; r[4]=acc[1][1]; r[5]=acc[1][2];
        }
        __syncthreads();
        if (kg == 0){
            const U64* r = Rs + q*6;
            float vals[4];
            #pragma unroll
            for (int i = 0; i < 2; i++){
                float2 gr = u2f(add2(acc[i][0], r[i*3+0]));
                float2 gz = u2f(add2(acc[i][1], r[i*3+1]));
                float2 gn = u2f(add2(acc[i][2], r[i*3+2]));
                #pragma unroll
                for (int rr = 0; rr < 2; rr++){
                    int j = 2*i + rr;
                    int rl = 4*slot + j;
                    float ghr = rr ? gr.y : gr.x;
                    float ghz = rr ? gz.y : gz.x;
                    float ghn = rr ? gn.y : gn.x;
                    float hpv = Hs[hcol*32 + rl];
                    float r_ = sigm(gR[j] + ghr + brv);
                    float z_ = sigm(gZ[j] + ghz + bzv);
                    float n_ = tanhf(gN[j] + r_*(ghn + bnv));
                    vals[j] = (1.f - z_)*n_ + z_*hpv;
                    H[(size_t)t*65536 + (nb+j)*256 + hcol] = vals[j];
                }
            }
            *(float4*)&d_Ht[(size_t)t*65536 + hcol*256 + nb] =
                make_float4(vals[0], vals[1], vals[2], vals[3]);
        }
        if (t+1 < T_){
            const int tn = t+1;
            const bool bd = (tn & 63) == 0;
            if (kg == 0 && !bd){
                #pragma unroll
                for (int j = 0; j < 4; j++){
                    const float* gi = GIc + ((size_t)tn*256 + nb + j)*768;
                    gR[j] = ldcg(gi + hcol); gZ[j] = ldcg(gi + 256 + hcol); gN[j] = ldcg(gi + 512 + hcol);
                }
            }
            __threadfence();
            __syncthreads();
            if (tid == 0){
                if ((tn & 127) == 0) atomicAdd(&d_progH, 1u);
                atomicAdd(&d_barC[grp*32], 1u);
                unsigned tg = 16u*tn;
                while (*(volatile unsigned*)&d_barC[grp*32] < tg) { }
                if (bd){
                    unsigned need = (unsigned)(tn >> 6) + 1u;
                    while (*(volatile unsigned*)&d_prog < need) { }
                }
                __threadfence();
            }
            __syncthreads();
            if (kg == 0 && bd){
                #pragma unroll
                for (int j = 0; j < 4; j++){
                    const float* gi = GIc + ((size_t)tn*256 + nb + j)*768;
                    gR[j] = ldcg(gi + hcol); gZ[j] = ldcg(gi + 256 + hcol); gN[j] = ldcg(gi + 512 + hcol);
                }
            }
        }
    }
    __threadfence();
    __syncthreads();
    if (tid == 0) atomicAdd(&d_progH, 1u);
}

// ===== persistent encoder chain (R9-proven) ======================================
__global__ void __launch_bounds__(256,1) enc_chain(
    const float* __restrict__ GIf, const float* __restrict__ GIb,
    const float* __restrict__ Wf,  const float* __restrict__ Wb,
    const float* __restrict__ bf,  const float* __restrict__ bb,
    float* __restrict__ Kout)
{
    extern __shared__ char sm[];
    U64*   Ws = (U64*)sm;
    float* Hs = (float*)(sm + 98304);
    const int tid = threadIdx.x;
    const int w = tid >> 5, l = tid & 31;
    const int colL = ((w & 1) << 3) + (l >> 2);
    const int r4   = ((w >> 1) << 2) + (l & 3);
    const int dir = blockIdx.x >> 6, b6 = blockIdx.x & 63;
    const int rbi = b6 >> 4, grp = dir*4 + rbi;
    const int rb = rbi*64, hcB = (b6 & 15)*16, hcol = hcB + colL;
    const float* W  = dir ? Wb  : Wf;
    const float* bh = dir ? bb  : bf;
    const float* GI = dir ? GIb : GIf;
    float* Kt = d_Kt + (size_t)dir*HR_*65536;
    for (int i = tid; i < 256*48; i += 256){
        int k = i/48, cc = i%48, g = cc>>4, c = cc&15;
        Ws[i] = pack_dup(W[(size_t)k*768 + g*256 + hcB + c]);
    }
    const float brv = bh[hcol], bzv = bh[256+hcol], bnv = bh[512+hcol];
    __syncthreads();
    for (int step = 0; step < HR_; step++){
        const int s = dir ? (HR_-1-step) : step;
        if (step == 0){
            for (int i = tid; i < 4096; i += 256)
                *(float4*)&Hs[i*4] = make_float4(0.f,0.f,0.f,0.f);
        } else {
            const int sp = dir ? (s+1) : (s-1);
            const float* hp = Kt + (size_t)sp*65536;
            for (int i = tid; i < 4096; i += 256){
                int c = i >> 4, rg = i & 15;
                float4 f = *(const float4*)&hp[(size_t)c*256 + rb + rg*4];
                *(float4*)&Hs[c*64 + rg*4] = f;
            }
        }
        __syncthreads();
        float gpr[4], gpz[4], gpn[4];
        #pragma unroll
        for (int i = 0; i < 4; i++){
            int n = rb + 4*r4 + i;
            const float* gi = GI + (size_t)(n*64 + s)*768;
            gpr[i] = gi[hcol]; gpz[i] = gi[256+hcol]; gpn[i] = gi[512+hcol];
        }
        U64 acc[2][3]; acc[0][0]=acc[0][1]=acc[0][2]=0ull; acc[1][0]=acc[1][1]=acc[1][2]=0ull;
        const U64* HsU = (const U64*)Hs;
        #pragma unroll 8
        for (int k = 0; k < 256; k++){
            U64 a0 = HsU[k*32 + 2*r4], a1 = HsU[k*32 + 2*r4 + 1];
            U64 b0 = Ws[k*48 + colL], b1 = Ws[k*48 + 16+colL], b2 = Ws[k*48 + 32+colL];
            acc[0][0]=fma2(a0,b0,acc[0][0]); acc[0][1]=fma2(a0,b1,acc[0][1]); acc[0][2]=fma2(a0,b2,acc[0][2]);
            acc[1][0]=fma2(a1,b0,acc[1][0]); acc[1][1]=fma2(a1,b1,acc[1][1]); acc[1][2]=fma2(a1,b2,acc[1][2]);
        }
        float vals[4];
        #pragma unroll
        for (int i = 0; i < 2; i++){
            float2 gr = u2f(acc[i][0]), gz = u2f(acc[i][1]), gn = u2f(acc[i][2]);
            #pragma unroll
            for (int rr = 0; rr < 2; rr++){
                int j = 2*i + rr;
                int rl = 4*r4 + j, n = rb + rl;
                float ghr = rr ? gr.y : gr.x, ghz = rr ? gz.y : gz.x, ghn = rr ? gn.y : gn.x;
                float hpv = Hs[hcol*64 + rl];
                float r_ = sigm(gpr[j] + ghr + brv);
                float z_ = sigm(gpz[j] + ghz + bzv);
                float n_ = tanhf(gpn[j] + r_*(ghn + bnv));
                vals[j] = (1.f - z_)*n_ + z_*hpv;
                Kout[(size_t)(n*64 + s)*512 + dir*256 + hcol] = vals[j];
            }
        }
        *(float4*)&Kt[(size_t)s*65536 + hcol*256 + rb + 4*r4] =
            make_float4(vals[0], vals[1], vals[2], vals[3]);
        if (step+1 < HR_){
            __threadfence();
            __syncthreads();
            if (tid == 0){
                atomicAdd(&d_barE[grp*32], 1u);
                unsigned tg = 16u*(step+1);
                while (*(volatile unsigned*)&d_barE[grp*32] < tg) { }
                __threadfence();
            }
            __syncthreads();
        }
    }
}

// ------ logits v2, chunked & gated on H progress: 128 timesteps per launch ------
__global__ void __launch_bounds__(256) logits_gemm2(int chunk)
{
    if (threadIdx.x == 0){
        unsigned need = 128u*(unsigned)(chunk+1);
        while (*(volatile unsigned*)&d_progH < need) __nanosleep(200);
    }
    __syncthreads();
    const int n  = blockIdx.y, m0 = chunk * 128;
    const float* Aq = d_H + (size_t)n*256;
    const float* Gn = d_G + (size_t)n*16384;
    __shared__ __align__(16) float As[16][128];
    __shared__ __align__(16) float Bs[16][64];
    const int tid = threadIdx.x, tx = tid & 15, ty = tid >> 4;
    U64 acc[4][4] = {};
    for (int k0 = 0; k0 < 256; k0 += 16){
        #pragma unroll
        for (int l = 0; l < 2; l++){
            int q = tid + l*256, row = q >> 2, c4 = q & 3;
            float4 f = ldcg4(&Aq[(size_t)(m0+row)*65536 + k0 + c4*4]);
            As[c4*4+0][row]=f.x; As[c4*4+1][row]=f.y; As[c4*4+2][row]=f.z; As[c4*4+3][row]=f.w;
        }
        {
            int srow = tid >> 2, c4 = tid & 3;
            float4 f = *(const float4*)&Gn[(size_t)srow*256 + k0 + c4*4];
            Bs[c4*4+0][srow]=f.x; Bs[c4*4+1][srow]=f.y; Bs[c4*4+2][srow]=f.z; Bs[c4*4+3][srow]=f.w;
        }
        __syncthreads();
        #pragma unroll
        for (int k = 0; k < 16; k++){
            const U64* ap = (const U64*)&As[k][ty*8];
            U64 a0=ap[0], a1=ap[1], a2=ap[2], a3=ap[3];
            float4 bv = *(const float4*)&Bs[k][tx*4];
            U64 b0=pack_dup(bv.x), b1=pack_dup(bv.y), b2=pack_dup(bv.z), b3=pack_dup(bv.w);
            acc[0][0]=fma2(a0,b0,acc[0][0]); acc[0][1]=fma2(a0,b1,acc[0][1]);
            acc[0][2]=fma2(a0,b2,acc[0][2]); acc[0][3]=fma2(a0,b3,acc[0][3]);
            acc[1][0]=fma2(a1,b0,acc[1][0]); acc[1][1]=fma2(a1,b1,acc[1][1]);
            acc[1][2]=fma2(a1,b2,acc[1][2]); acc[1][3]=fma2(a1,b3,acc[1][3]);
            acc[2][0]=fma2(a2,b0,acc[2][0]); acc[2][1]=fma2(a2,b1,acc[2][1]);
            acc[2][2]=fma2(a2,b2,acc[2][2]); acc[2][3]=fma2(a2,b3,acc[2][3]);
            acc[3][0]=fma2(a3,b0,acc[3][0]); acc[3][1]=fma2(a3,b1,acc[3][1]);
            acc[3][2]=fma2(a3,b2,acc[3][2]); acc[3][3]=fma2(a3,b3,acc[3][3]);
        }
        __syncthreads();
    }
    float4 cc = *(const float4*)&d_cv[n*64 + tx*4];
    float cj[4] = {cc.x, cc.y, cc.z, cc.w};
    #pragma unroll
    for (int p = 0; p < 4; p++){
        int t0 = m0 + ty*8 + p*2;
        #pragma unroll
        for (int j = 0; j < 4; j++){
            float2 v = u2f(acc[p][j]);
            d_Lg[((size_t)t0*256 + n)*64 + tx*4 + j]     = v.x + cj[j];
            d_Lg[((size_t)(t0+1)*256 + n)*64 + tx*4 + j] = v.y + cj[j];
        }
    }
}

__global__ void __launch_bounds__(256) pack_out(
    int wbase,
    const int* __restrict__ actions,
    const float* __restrict__ critic_W, const float* __restrict__ critic_b,
    float* __restrict__ out)
{
    int wid = wbase + blockIdx.x*8 + (threadIdx.x >> 5), lane = threadIdx.x & 31;
    const float* h  = d_H  + (size_t)wid*256;
    const float* lg = d_Lg + (size_t)wid*64;
    float* o = out + (size_t)wid*322;
    float c = 0.f;
    #pragma unroll
    for (int j = 0; j < 8; j++){ int k = lane + j*32; c += h[k]*critic_W[k]; }
    #pragma unroll
    for (int s = 16; s > 0; s >>= 1) c += __shfl_xor_sync(0xffffffffu, c, s);
    #pragma unroll
    for (int j = 0; j < 8; j++){ int k = lane + j*32; o[2 + k] = h[k]; }
    float x0 = lg[lane], x1 = lg[lane + 32];
    float m = fmaxf(x0, x1);
    #pragma unroll
    for (int s = 16; s > 0; s >>= 1) m = fmaxf(m, __shfl_xor_sync(0xffffffffu, m, s));
    float e0 = expf(x0 - m), e1 = expf(x1 - m);
    float ssum = e0 + e1;
    #pragma unroll
    for (int s = 16; s > 0; s >>= 1) ssum += __shfl_xor_sync(0xffffffffu, ssum, s);
    float inv = 1.f / ssum;
    o[258 + lane] = e0 * inv;
    o[290 + lane] = e1 * inv;
    if (lane == 0){ o[0] = (float)actions[wid]; o[1] = c + critic_b[0]; }
}

extern "C" void kernel_launch(void* const* d_in, const int* in_sizes, int n_in,
                              void* d_out, int out_size)
{
    const float* values   = (const float*)d_in[0];
    const float* mdp      = (const float*)d_in[1];
    const int*   actions  = (const int*)  d_in[2];
    const int*   a0       = (const int*)  d_in[3];
    const float* h0       = (const float*)d_in[4];
    const float* emb_W    = (const float*)d_in[5];
    const float* emb_b    = (const float*)d_in[6];
    const float* gfw_Wih  = (const float*)d_in[7];
    const float* gfw_Whh  = (const float*)d_in[8];
    const float* gfw_bih  = (const float*)d_in[9];
    const float* gfw_bhh  = (const float*)d_in[10];
    const float* gbw_Wih  = (const float*)d_in[11];
    const float* gbw_Whh  = (const float*)d_in[12];
    const float* gbw_bih  = (const float*)d_in[13];
    const float* gbw_bhh  = (const float*)d_in[14];
    const float* f0_W     = (const float*)d_in[15];
    const float* f0_b     = (const float*)d_in[16];
    const float* f1_W     = (const float*)d_in[17];
    const float* f1_b     = (const float*)d_in[18];
    const float* cell_Wih = (const float*)d_in[19];
    const float* cell_Whh = (const float*)d_in[20];
    const float* cell_bih = (const float*)d_in[21];
    const float* cell_bhh = (const float*)d_in[22];
    const float* critic_W = (const float*)d_in[23];
    const float* critic_b = (const float*)d_in[24];
    const float* qg_W     = (const float*)d_in[25];
    const float* qg_b     = (const float*)d_in[26];
    float* out = (float*)d_out;

    float *pM, *pGIf, *pGIb, *pK, *pXin, *pX0, *pX1, *pGIc, *pH, *pG, *pWt, *pZ;
    cudaGetSymbolAddress((void**)&pM,   d_M);
    cudaGetSymbolAddress((void**)&pGIf, d_GIf);
    cudaGetSymbolAddress((void**)&pGIb, d_GIb);
    cudaGetSymbolAddress((void**)&pK,   d_K);
    cudaGetSymbolAddress((void**)&pXin, d_Xin);
    cudaGetSymbolAddress((void**)&pX0,  d_X0);
    cudaGetSymbolAddress((void**)&pX1,  d_X1);
    cudaGetSymbolAddress((void**)&pGIc, d_GIc);
    cudaGetSymbolAddress((void**)&pH,   d_H);
    cudaGetSymbolAddress((void**)&pG,   d_G);
    cudaGetSymbolAddress((void**)&pWt,  d_Wt);
    cudaGetSymbolAddress((void**)&pZ,   d_Z);

    cudaFuncSetAttribute(enc_chain,  cudaFuncAttributeMaxDynamicSharedMemorySize, 163840);
    cudaFuncSetAttribute(cell_chain, cudaFuncAttributeMaxDynamicSharedMemorySize, 163840);

    static cudaStream_t sB = 0;
    static cudaEvent_t evM = 0, evEnc = 0, evTail = 0;
    if (!sB){
        cudaStreamCreateWithFlags(&sB, cudaStreamNonBlocking);
        cudaEventCreateWithFlags(&evM,    cudaEventDisableTiming);
        cudaEventCreateWithFlags(&evEnc,  cudaEventDisableTiming);
        cudaEventCreateWithFlags(&evTail, cudaEventDisableTiming);
    }

    // ---- stream 0: M, GIf/GIb, enc (clean window), then the cell chain ---------
    zero_bars<<<1,256>>>();
    gemm_nn<false><<<dim3(4,128), 256>>>(mdp, 128, emb_W, 256, emb_b, pM, 256, 128);
    cudaEventRecord(evM, 0);
    gemm_nn<false><<<dim3(12,128), 256>>>(pM, 256, gfw_Wih, 768, gfw_bih, pGIf, 768, 256);
    gemm_nn<false><<<dim3(12,128), 256>>>(pM, 256, gbw_Wih, 768, gbw_bih, pGIb, 768, 256);
    enc_chain<<<128, 256, 163840>>>(pGIf, pGIb, gfw_Whh, gbw_Whh, gfw_bhh, gbw_bhh, pK);
    cudaEventRecord(evEnc, 0);
    cell_chain<<<128, 256, 137280>>>(pGIc, h0, cell_Whh, cell_bhh, pH);

    // ---- sB: gather + chunk-0 producer hidden under GIf/GIb; rest after enc ----
    cudaStreamWaitEvent(sB, evM, 0);
    gather_xin<<<(T_*N_*80 + 255)/256, 256, 0, sB>>>(values, actions, a0);
    {   // chunk 0 only (ready before the cell chain starts)
        gemm_nn<true ><<<dim3(4,128), 256, 0, sB>>>(
            pXin, 320, f0_W, 256, f0_b, pX0, 256, 320);
        gemm_nn<true ><<<dim3(4,128), 256, 0, sB>>>(
            pX0, 256, f1_W, 256, f1_b, pX1, 256, 256);
        gemm_nn<false><<<dim3(12,128), 256, 0, sB>>>(
            pX1, 256, cell_Wih, 768, cell_bih, pGIc, 768, 256);
        set_prog<<<1,1,0,sB>>>(1u);
    }
    cudaStreamWaitEvent(sB, evEnc, 0);
    for (int c = 1; c < 8; c++){
        const size_t r0 = (size_t)c*16384;
        gemm_nn<true ><<<dim3(4,128), 256, 0, sB>>>(
            pXin + r0*320, 320, f0_W, 256, f0_b, pX0 + r0*256, 256, 320);
        gemm_nn<true ><<<dim3(4,128), 256, 0, sB>>>(
            pX0 + r0*256, 256, f1_W, 256, f1_b, pX1 + r0*256, 256, 256);
        gemm_nn<false><<<dim3(12,128), 256, 0, sB>>>(
            pX1 + r0*256, 256, cell_Wih, 768, cell_bih, pGIc + r0*768, 768, 256);
        set_prog<<<1,1,0,sB>>>((unsigned)(c+1));
    }
    transpose_qgw<<<512, 256, 0, sB>>>(qg_W);
    calc_cvec<<<2048, 256, 0, sB>>>(qg_b);
    gemm_nn<false><<<dim3(4,128), 256, 0, sB>>>(pK, 512, pWt, 256, pZ, pG, 256, 512);
    for (int c = 0; c < 4; c++){
        logits_gemm2<<<dim3(1,256), 256, 0, sB>>>(c);
        pack_out<<<4096, 256, 0, sB>>>(c*32768, actions, critic_W, critic_b, out);
    }
    cudaEventRecord(evTail, sB);

    // join sB into stream 0
    cudaStreamWaitEvent(0, evTail, 0);
}